// round 5
// baseline (speedup 1.0000x reference)
#include <cuda_runtime.h>
#include <math.h>

// ---- problem constants ----
#define Vv    32000
#define Cc    768
#define Tt    1024
#define Bb    4
#define Hh    12
#define HSs   64
#define FFf   9216
#define NB    3
#define Mrows 4096            // B*T
#define LOGITS_N 131072000LL  // Mrows * Vv
#define ATT_SCALE 0.036084391824351615f  // 768^-0.5

// ---- scratch (device globals; no runtime allocation) ----
__device__ float g_x [Mrows*Cc];
__device__ float g_h [Mrows*Cc];
__device__ float g_q [Mrows*Cc];
__device__ float g_k [Mrows*Cc];
__device__ float g_v [Mrows*Cc];
__device__ float g_o [Mrows*Cc];
__device__ float g_ff[Mrows*FFf];
__device__ float g_wpack[NB*3*Cc*Cc];
__device__ float g_rowloss[Mrows];

// ============================================================
// pack wq/wk/wv: [blk][H][C][HS] -> [blk][mat][C][H*HS] row-major
// ============================================================
__global__ void pack_qkv_kernel(const float* __restrict__ wq,
                                const float* __restrict__ wk,
                                const float* __restrict__ wv) {
    int idx = blockIdx.x * blockDim.x + threadIdx.x;
    const int per = Cc * Cc;
    if (idx >= NB * 3 * per) return;
    int which = idx / per;      // 0..8
    int e     = idx % per;
    int blk = which / 3, mat = which % 3;
    int c = e / Cc, j = e % Cc;
    int h = j / HSs, d = j % HSs;
    const float* src = (mat == 0) ? wq : (mat == 1) ? wk : wv;
    g_wpack[(size_t)which * per + e] = src[(((size_t)blk*Hh + h)*Cc + c)*HSs + d];
}

// ============================================================
// embed: x[r,c] = tok_emb[sources[r], c] + pos_emb[r%T, c]
// ============================================================
__global__ void embed_kernel(const float* __restrict__ tok,
                             const float* __restrict__ pos,
                             const int* __restrict__ src) {
    int idx = blockIdx.x * blockDim.x + threadIdx.x;
    if (idx >= Mrows * Cc) return;
    int r = idx / Cc, c = idx % Cc;
    int t = r % Tt;
    g_x[idx] = tok[(size_t)src[r]*Cc + c] + pos[(size_t)t*Cc + c];
}

// ============================================================
// row LayerNorm: out = (x - mean)*rsqrt(var+eps)*g + b   (row = 768)
// grid = Mrows, block = 256
// ============================================================
__global__ void ln_kernel(const float* __restrict__ x,
                          const float* __restrict__ g,
                          const float* __restrict__ b,
                          float* __restrict__ out) {
    int r = blockIdx.x;
    int tid = threadIdx.x;
    const float* xr = x + (size_t)r * Cc;
    float vals[3];
    float s = 0.f, ss = 0.f;
#pragma unroll
    for (int i = 0; i < 3; i++) {
        float v = xr[tid + i*256];
        vals[i] = v; s += v; ss += v*v;
    }
#pragma unroll
    for (int o = 16; o; o >>= 1) {
        s  += __shfl_xor_sync(0xffffffffu, s,  o);
        ss += __shfl_xor_sync(0xffffffffu, ss, o);
    }
    __shared__ float sh_s[8], sh_ss[8];
    __shared__ float smean, srstd;
    int w = tid >> 5, l = tid & 31;
    if (l == 0) { sh_s[w] = s; sh_ss[w] = ss; }
    __syncthreads();
    if (tid == 0) {
        float S = 0.f, SS = 0.f;
        for (int i = 0; i < 8; i++) { S += sh_s[i]; SS += sh_ss[i]; }
        float m = S / Cc;
        float var = SS / Cc - m * m;
        smean = m; srstd = rsqrtf(var + 1e-5f);
    }
    __syncthreads();
    float m = smean, rstd = srstd;
#pragma unroll
    for (int i = 0; i < 3; i++) {
        int c = tid + i*256;
        out[(size_t)r*Cc + c] = (vals[i] - m) * rstd * g[c] + b[c];
    }
}

// ============================================================
// SGEMM: C = A[M,K] @ B[K,N] (+bias) (+relu / +residual)
// 128x128 tile, BK=16, 256 threads, 8x8 per thread.
// Requires M%128==0, N%128==0, K%16==0 (true for all shapes here).
// mode: 0 = bias+store, 1 = relu(bias+acc), 2 = res + acc + bias
// ============================================================
__global__ void __launch_bounds__(256)
sgemm_kernel(const float* __restrict__ A, const float* __restrict__ B,
             const float* __restrict__ bias, const float* __restrict__ res,
             float* __restrict__ C, int M, int N, int K, int mode) {
    __shared__ __align__(16) float As[16][128];   // transposed A tile
    __shared__ __align__(16) float Bs[16][128];
    int tid = threadIdx.x;
    int tr = tid >> 4, tc = tid & 15;
    int by = blockIdx.y, bx = blockIdx.x;
    const float* Ab  = A + (size_t)by * 128 * K;
    const float* Bb_ = B + (size_t)bx * 128;

    float acc[8][8];
#pragma unroll
    for (int i = 0; i < 8; i++)
#pragma unroll
        for (int j = 0; j < 8; j++) acc[i][j] = 0.f;

    int arow = tid >> 2;         // 0..63
    int akc  = (tid & 3) * 4;    // 0,4,8,12
    int bk   = tid >> 4;         // 0..15
    int bc   = (tid & 15) * 8;   // 0..120

    for (int k0 = 0; k0 < K; k0 += 16) {
#pragma unroll
        for (int it = 0; it < 2; it++) {
            int row = arow + it * 64;
            float4 av = *(const float4*)(Ab + (size_t)row * K + k0 + akc);
            As[akc+0][row] = av.x; As[akc+1][row] = av.y;
            As[akc+2][row] = av.z; As[akc+3][row] = av.w;
        }
        float4 bv0 = *(const float4*)(Bb_ + (size_t)(k0 + bk) * N + bc);
        float4 bv1 = *(const float4*)(Bb_ + (size_t)(k0 + bk) * N + bc + 4);
        *(float4*)&Bs[bk][bc]     = bv0;
        *(float4*)&Bs[bk][bc + 4] = bv1;
        __syncthreads();
#pragma unroll
        for (int k = 0; k < 16; k++) {
            float a[8], bfr[8];
            *(float4*)&a[0]   = *(const float4*)&As[k][tr*8];
            *(float4*)&a[4]   = *(const float4*)&As[k][tr*8 + 4];
            *(float4*)&bfr[0] = *(const float4*)&Bs[k][tc*8];
            *(float4*)&bfr[4] = *(const float4*)&Bs[k][tc*8 + 4];
#pragma unroll
            for (int i = 0; i < 8; i++)
#pragma unroll
                for (int j = 0; j < 8; j++)
                    acc[i][j] += a[i] * bfr[j];
        }
        __syncthreads();
    }

    int row0 = by*128 + tr*8, col0 = bx*128 + tc*8;
#pragma unroll
    for (int i = 0; i < 8; i++) {
#pragma unroll
        for (int j = 0; j < 8; j++) {
            float v = acc[i][j];
            if (bias) v += bias[col0 + j];
            if (mode == 1) v = fmaxf(v, 0.f);
            else if (mode == 2) v += res[(size_t)(row0 + i) * N + col0 + j];
            C[(size_t)(row0 + i) * N + col0 + j] = v;
        }
    }
}

// ============================================================
// fused causal attention, fp32, online softmax.
// q/k/v/o layout: [B, T, C] with head h occupying cols [h*64, h*64+64)
// grid = (B*H, T/64), block = 256.
// ============================================================
__global__ void __launch_bounds__(256)
attn_kernel(const float* __restrict__ Q, const float* __restrict__ K,
            const float* __restrict__ V, float* __restrict__ O) {
    int bh = blockIdx.x;
    int b = bh / Hh, h = bh % Hh;
    int qt0 = blockIdx.y * 64;
    int tid = threadIdx.x;

    __shared__ float Qs[64][64];
    __shared__ float Ks[32][65];
    __shared__ float Vs[32][65];
    __shared__ float Ps[64][33];
    __shared__ float mrow[64], lrow[64], arow_s[64];

    // load Q tile (coalesced)
#pragma unroll
    for (int i = 0; i < 16; i++) {
        int e = tid + i*256;
        int r = e >> 6, d = e & 63;
        Qs[r][d] = Q[((size_t)(b*Tt + qt0 + r))*Cc + h*64 + d];
    }
    if (tid < 64) { mrow[tid] = -1e30f; lrow[tid] = 0.f; }

    float o[16];
#pragma unroll
    for (int i = 0; i < 16; i++) o[i] = 0.f;

    int d_o  = tid & 63;   // O column
    int rg_o = tid >> 6;   // O row group (x16)
    int s_s  = tid & 31;   // S column
    int rg_s = tid >> 5;   // S row group (x8)

    int nkt = (qt0 + 64) / 32;
    for (int kt = 0; kt < nkt; kt++) {
        __syncthreads();
        // load K/V tiles (32x64 each)
#pragma unroll
        for (int i = 0; i < 8; i++) {
            int e = tid + i*256;
            int s = e >> 6, d = e & 63;
            size_t gi = ((size_t)(b*Tt + kt*32 + s))*Cc + h*64 + d;
            Ks[s][d] = K[gi];
            Vs[s][d] = V[gi];
        }
        __syncthreads();
        // S = Q K^T * scale (+ causal mask)
#pragma unroll
        for (int i = 0; i < 8; i++) {
            int r = rg_s*8 + i;
            float a = 0.f;
#pragma unroll
            for (int k = 0; k < 64; k++) a += Qs[r][k] * Ks[s_s][k];
            int sg = kt*32 + s_s, tg = qt0 + r;
            Ps[r][s_s] = (sg <= tg) ? a * ATT_SCALE : -1e30f;
        }
        __syncthreads();
        // online softmax stats (one thread per row)
        if (tid < 64) {
            int r = tid;
            float m_old = mrow[r];
            float mx = m_old;
#pragma unroll
            for (int s = 0; s < 32; s++) mx = fmaxf(mx, Ps[r][s]);
            float alpha = expf(m_old - mx);
            float sum = 0.f;
#pragma unroll
            for (int s = 0; s < 32; s++) {
                float p = expf(Ps[r][s] - mx);
                Ps[r][s] = p; sum += p;
            }
            mrow[r] = mx;
            lrow[r] = lrow[r] * alpha + sum;
            arow_s[r] = alpha;
        }
        __syncthreads();
        // O = O*alpha + P V
#pragma unroll
        for (int i = 0; i < 16; i++) {
            int r = rg_o*16 + i;
            float al = arow_s[r];
            float a = 0.f;
#pragma unroll
            for (int s = 0; s < 32; s++) a += Ps[r][s] * Vs[s][d_o];
            o[i] = o[i] * al + a;
        }
    }
    // write normalized output
#pragma unroll
    for (int i = 0; i < 16; i++) {
        int r = rg_o*16 + i;
        O[((size_t)(b*Tt + qt0 + r))*Cc + h*64 + d_o] = o[i] / lrow[r];
    }
}

// ============================================================
// loss: per-row log-softmax NLL, then mean
// ============================================================
__global__ void loss_rows_kernel(const float* __restrict__ logits,
                                 const int* __restrict__ targets) {
    int r = blockIdx.x, tid = threadIdx.x;
    const float* row = logits + (size_t)r * Vv;
    __shared__ float sh[8];
    __shared__ float bmax;
    float mx = -1e30f;
    for (int c = tid; c < Vv; c += 256) mx = fmaxf(mx, row[c]);
#pragma unroll
    for (int o = 16; o; o >>= 1) mx = fmaxf(mx, __shfl_xor_sync(0xffffffffu, mx, o));
    if ((tid & 31) == 0) sh[tid >> 5] = mx;
    __syncthreads();
    if (tid == 0) {
        float m = sh[0];
        for (int i = 1; i < 8; i++) m = fmaxf(m, sh[i]);
        bmax = m;
    }
    __syncthreads();
    mx = bmax;
    float s = 0.f;
    for (int c = tid; c < Vv; c += 256) s += expf(row[c] - mx);
#pragma unroll
    for (int o = 16; o; o >>= 1) s += __shfl_xor_sync(0xffffffffu, s, o);
    if ((tid & 31) == 0) sh[tid >> 5] = s;
    __syncthreads();
    if (tid == 0) {
        float S = 0.f;
        for (int i = 0; i < 8; i++) S += sh[i];
        g_rowloss[r] = mx + logf(S) - row[targets[r]];
    }
}

__global__ void loss_reduce_kernel(float* __restrict__ d_out, long long out_size) {
    int tid = threadIdx.x;
    __shared__ float sh[8];
    float s = 0.f;
    for (int i = tid; i < Mrows; i += 256) s += g_rowloss[i];
#pragma unroll
    for (int o = 16; o; o >>= 1) s += __shfl_xor_sync(0xffffffffu, s, o);
    if ((tid & 31) == 0) sh[tid >> 5] = s;
    __syncthreads();
    if (tid == 0) {
        float S = 0.f;
        for (int i = 0; i < 8; i++) S += sh[i];
        float loss = S / (float)Mrows;
        for (long long i = LOGITS_N; i < out_size; i++) d_out[i] = loss;
    }
}

// ============================================================
// host orchestration
// ============================================================
extern "C" void kernel_launch(void* const* d_in, const int* in_sizes, int n_in,
                              void* d_out, int out_size) {
    const float* tok_emb = (const float*)d_in[0];
    const float* pos_emb = (const float*)d_in[1];
    const float* wq      = (const float*)d_in[2];
    const float* wk      = (const float*)d_in[3];
    const float* wv      = (const float*)d_in[4];
    const float* wproj   = (const float*)d_in[5];
    const float* bproj   = (const float*)d_in[6];
    const float* g1      = (const float*)d_in[7];
    const float* b1      = (const float*)d_in[8];
    const float* g2      = (const float*)d_in[9];
    const float* b2      = (const float*)d_in[10];
    const float* wf1     = (const float*)d_in[11];
    const float* bf1     = (const float*)d_in[12];
    const float* wf2     = (const float*)d_in[13];
    const float* bf2     = (const float*)d_in[14];
    const float* gf      = (const float*)d_in[15];
    const float* bfv     = (const float*)d_in[16];
    const float* wlm     = (const float*)d_in[17];
    const float* blm     = (const float*)d_in[18];
    const int*   sources = (const int*)d_in[19];
    const int*   targets = (const int*)d_in[20];
    float* out = (float*)d_out;

    float *px, *ph, *pq, *pk, *pv, *po, *pff, *pwp;
    cudaGetSymbolAddress((void**)&px,  g_x);
    cudaGetSymbolAddress((void**)&ph,  g_h);
    cudaGetSymbolAddress((void**)&pq,  g_q);
    cudaGetSymbolAddress((void**)&pk,  g_k);
    cudaGetSymbolAddress((void**)&pv,  g_v);
    cudaGetSymbolAddress((void**)&po,  g_o);
    cudaGetSymbolAddress((void**)&pff, g_ff);
    cudaGetSymbolAddress((void**)&pwp, g_wpack);

    pack_qkv_kernel<<<(NB*3*Cc*Cc + 255)/256, 256>>>(wq, wk, wv);
    embed_kernel<<<(Mrows*Cc + 255)/256, 256>>>(tok_emb, pos_emb, sources);

    dim3 gcc(Cc/128, Mrows/128);      // 768-wide GEMMs
    dim3 gff(FFf/128, Mrows/128);     // FF1
    dim3 glm(Vv/128, Mrows/128);      // LM head

    for (int i = 0; i < NB; i++) {
        ln_kernel<<<Mrows, 256>>>(px, g1 + i*Cc, b1 + i*Cc, ph);

        sgemm_kernel<<<gcc, 256>>>(ph, pwp + (size_t)(i*3+0)*Cc*Cc, nullptr, nullptr,
                                   pq, Mrows, Cc, Cc, 0);
        sgemm_kernel<<<gcc, 256>>>(ph, pwp + (size_t)(i*3+1)*Cc*Cc, nullptr, nullptr,
                                   pk, Mrows, Cc, Cc, 0);
        sgemm_kernel<<<gcc, 256>>>(ph, pwp + (size_t)(i*3+2)*Cc*Cc, nullptr, nullptr,
                                   pv, Mrows, Cc, Cc, 0);

        attn_kernel<<<dim3(Bb*Hh, Tt/64), 256>>>(pq, pk, pv, po);

        sgemm_kernel<<<gcc, 256>>>(po, wproj + (size_t)i*Cc*Cc, bproj + i*Cc, px,
                                   px, Mrows, Cc, Cc, 2);

        ln_kernel<<<Mrows, 256>>>(px, g2 + i*Cc, b2 + i*Cc, ph);

        sgemm_kernel<<<gff, 256>>>(ph, wf1 + (size_t)i*Cc*FFf, bf1 + i*FFf, nullptr,
                                   pff, Mrows, FFf, Cc, 1);
        sgemm_kernel<<<gcc, 256>>>(pff, wf2 + (size_t)i*FFf*Cc, bf2 + i*Cc, px,
                                   px, Mrows, Cc, FFf, 2);
    }

    ln_kernel<<<Mrows, 256>>>(px, gf, bfv, ph);
    sgemm_kernel<<<glm, 256>>>(ph, wlm, blm, nullptr, out, Mrows, Vv, Cc, 0);

    loss_rows_kernel<<<Mrows, 256>>>(out, targets);
    loss_reduce_kernel<<<1, 256>>>(out, (long long)out_size);
}